// round 14
// baseline (speedup 1.0000x reference)
#include <cuda_runtime.h>
#include <cuda_fp16.h>
#include <cstdint>

#define DI __device__ __forceinline__

// ---------------- problem constants ----------------
constexpr int BATCH   = 16384;
constexpr int INF     = 512;
constexpr int OUTF    = 512;
constexpr int NG      = 8;
constexpr int KTOT    = INF * NG;    // 4096
constexpr int KC      = 64;          // K per chunk (128B fp16 row)
constexpr int NCH     = KTOT / KC;   // 64 chunks
constexpr int NT      = 128;         // N tile per CTA
constexpr int THREADS = 128;         // 4 warps
constexpr int STAGES  = 2;

// mixed-size M tiling: 136 big tiles (64 rows) + 160 small tiles (48 rows)
// 136*64 + 160*48 = 16384; total tiles = (136+160)*4 = 1184 = 2 * (148*4)
constexpr int NBIG      = 136;
constexpr int NSMALL    = 160;
constexpr int BIG_CTAS  = NBIG * 4;      // 544
constexpr int GRID      = (NBIG + NSMALL) * 4;  // 1184
constexpr int SMALL_M0  = NBIG * 64;     // 8704

constexpr int A_BYTES     = 64 * 128;             // 8 KB
constexpr int B_BYTES     = 128 * 128;            // 16 KB
constexpr int STAGE_BYTES = A_BYTES + B_BYTES;    // 24 KB
constexpr int SMEM_DYN    = STAGES * STAGE_BYTES + 1024;   // ~49 KB -> 4 CTAs/SM

// fp16 W transposed to [OUTF, KTOT], K contiguous
__device__ __half g_Wt[(size_t)OUTF * KTOT];

// ---------------- PTX helpers ----------------
DI uint32_t smem_u32(const void* p) {
    uint32_t a;
    asm("{ .reg .u64 t; cvta.to.shared.u64 t, %1; cvt.u32.u64 %0, t; }" : "=r"(a) : "l"(p));
    return a;
}

// pack (lo,hi) fp32 -> f16x2 and take 2^x on both halves in one MUFU op
DI uint32_t ex2_f16x2(float lo, float hi) {
    uint32_t d;
    asm("{ .reg .b32 t; cvt.rn.f16x2.f32 t, %1, %2; ex2.approx.f16x2 %0, t; }"
        : "=r"(d) : "f"(hi), "f"(lo));
    return d;
}

DI uint32_t swz(uint32_t off) { return off ^ ((off >> 3) & 0x70u); }

DI void ldmx4(uint32_t* r, uint32_t addr) {
    asm volatile("ldmatrix.sync.aligned.m8n8.x4.shared.b16 {%0,%1,%2,%3}, [%4];"
                 : "=r"(r[0]), "=r"(r[1]), "=r"(r[2]), "=r"(r[3]) : "r"(addr));
}

DI void mma16816(float* c, const uint32_t* a, const uint32_t* b) {
    asm volatile(
        "mma.sync.aligned.m16n8k16.row.col.f32.f16.f16.f32 "
        "{%0,%1,%2,%3}, {%4,%5,%6,%7}, {%8,%9}, {%0,%1,%2,%3};"
        : "+f"(c[0]), "+f"(c[1]), "+f"(c[2]), "+f"(c[3])
        : "r"(a[0]), "r"(a[1]), "r"(a[2]), "r"(a[3]), "r"(b[0]), "r"(b[1]));
}

DI void cp_async16(uint32_t dst, const void* src) {
    asm volatile("cp.async.cg.shared.global [%0], [%1], 16;" :: "r"(dst), "l"(src) : "memory");
}
#define CP_COMMIT() asm volatile("cp.async.commit_group;" ::: "memory")
#define CP_WAIT0()  asm volatile("cp.async.wait_group 0;" ::: "memory")

// ---------------- kernel 1: W[K,N] f32 -> Wt[N,K] fp16 ----------------
__global__ void wt_kernel(const float* __restrict__ W) {
    __shared__ float tile[32][33];
    int k0 = blockIdx.x * 32, n0 = blockIdx.y * 32;
    int tx = threadIdx.x, ty = threadIdx.y;
#pragma unroll
    for (int i = 0; i < 32; i += 8)
        tile[ty + i][tx] = W[(size_t)(k0 + ty + i) * OUTF + n0 + tx];
    __syncthreads();
#pragma unroll
    for (int i = 0; i < 32; i += 8)
        g_Wt[(size_t)(n0 + ty + i) * KTOT + k0 + tx] = __float2half_rn(tile[tx][ty + i]);
}

// ---------------- kernel 2: fused basis + mma.sync GEMM ----------------

// B tile: 8 cp.async per thread; dst/src affine in slice index i
DI void produce_B(uint32_t bDst, const __half* bSrc) {
#pragma unroll
    for (int i = 0; i < 8; i++)
        cp_async16(bDst + i * 2048, (const void*)(bSrc + (size_t)i * 16 * KTOT));
}

// A slice: one feature -> 8 gaussian values -> one 16B store
DI void produce_A_slice(uint32_t aDst, const float* nb, float aco, float xf) {
    uint32_t pk[4];
#pragma unroll
    for (int q = 0; q < 4; q++) {
        float v0 = fmaf(xf, aco, nb[2 * q]);
        float v1 = fmaf(xf, aco, nb[2 * q + 1]);
        // exp(-u^2) = 2^(-(u*sqrt(log2 e))^2); both halves in one MUFU
        pk[q] = ex2_f16x2(-(v0 * v0), -(v1 * v1));
    }
    asm volatile("st.shared.v4.b32 [%0], {%1, %2, %3, %4};"
                 :: "r"(aDst), "r"(pk[0]), "r"(pk[1]), "r"(pk[2]), "r"(pk[3])
                 : "memory");
}

__global__ void __launch_bounds__(THREADS, 4)
gk_kernel(const float* __restrict__ x, const float* __restrict__ grid,
          float* __restrict__ out)
{
    extern __shared__ char smem[];
    uint32_t sb = (smem_u32(smem) + 1023u) & ~1023u;

    int tid  = threadIdx.x;
    int lane = tid & 31;
    int wid  = tid >> 5;
    int bid  = blockIdx.x;

    // mixed tiling: big (64-row) tiles first, then small (48-row)
    bool big;
    int Mstart, Ntile;
    if (bid < BIG_CTAS) {
        big = true;
        Ntile  = bid / NBIG;
        Mstart = (bid - Ntile * NBIG) * 64;
    } else {
        big = false;
        int b2 = bid - BIG_CTAS;
        Ntile  = b2 / NSMALL;
        Mstart = SMALL_M0 + (b2 - Ntile * NSMALL) * 48;
    }

    float aco = 1.75f * 1.2011224087864498f;   // (1/h)*sqrt(log2 e), h = 4/7
    float nb[8];
#pragma unroll
    for (int g = 0; g < 8; g++) nb[g] = -grid[g] * aco;

    uint32_t aBuf[STAGES], bBuf[STAGES];
#pragma unroll
    for (int s = 0; s < STAGES; s++) {
        aBuf[s] = sb + s * STAGE_BYTES;
        bBuf[s] = aBuf[s] + A_BYTES;
    }

    // ---- hoisted producer state ----
    int n0  = tid >> 3, seg = tid & 7;
    uint32_t bD0 = swz((uint32_t)(n0 * 128 + seg * 16));   // slice-invariant swizzle
    const __half* bSrcNext = g_Wt + (size_t)(Ntile * NT + n0) * KTOT + seg * 8;
    int m = tid >> 1, half = tid & 1;
    bool aprod = big || (m < 48);              // warp-uniform: warp 3 idles on small tiles
    uint32_t aDsw[4];
#pragma unroll
    for (int sl = 0; sl < 4; sl++)
        aDsw[sl] = swz((uint32_t)(m * 128 + (half * 4 + sl) * 16));
    const float* xNext = x + (size_t)(Mstart + (aprod ? m : 0)) * INF + half * 4;

    // warp tiling: 4 warps = 1(M) x 4(N); warp tile 64x32 (48x32 on small)
    int wn = wid;

    uint32_t aOff[4], bOff[2];
#pragma unroll
    for (int mi = 0; mi < 4; mi++) {
        int row = mi * 16 + (lane & 15);
        int u   = lane >> 4;
        aOff[mi] = swz((uint32_t)(row * 128 + u * 16));
    }
#pragma unroll
    for (int p = 0; p < 2; p++) {
        int row = wn * 32 + p * 16 + ((lane >> 4) & 1) * 8 + (lane & 7);
        int u   = (lane >> 3) & 1;
        bOff[p] = swz((uint32_t)(row * 128 + u * 16));
    }

    float acc[4][4][4];
#pragma unroll
    for (int mi = 0; mi < 4; mi++)
#pragma unroll
        for (int ni = 0; ni < 4; ni++)
#pragma unroll
            for (int q = 0; q < 4; q++) acc[mi][ni][q] = 0.0f;

    // prologue: stage chunk 0; prefetch x for chunk 1
    float xsN[4];
    {
        produce_B(bBuf[0] + bD0, bSrcNext);
        bSrcNext += KC;
        float4 x0 = make_float4(0.f, 0.f, 0.f, 0.f);
        if (aprod) x0 = *reinterpret_cast<const float4*>(xNext);
        xNext += NG;
        float xs0[4] = {x0.x, x0.y, x0.z, x0.w};
        if (aprod) {
#pragma unroll
            for (int sl = 0; sl < 4; sl++)
                produce_A_slice(aBuf[0] + aDsw[sl], nb, aco, xs0[sl]);
        }
        CP_COMMIT();
        float4 x1 = make_float4(0.f, 0.f, 0.f, 0.f);
        if (aprod) x1 = *reinterpret_cast<const float4*>(xNext);
        xNext += NG;
        xsN[0] = x1.x; xsN[1] = x1.y; xsN[2] = x1.z; xsN[3] = x1.w;
    }

    for (int c = 0; c < NCH; c++) {
        CP_WAIT0();
        __syncthreads();

        int cur = c & 1;
        bool doprod = (c + 1 < NCH);
        if (doprod) {
            produce_B(bBuf[cur ^ 1] + bD0, bSrcNext);
            bSrcNext += KC;
            CP_COMMIT();
            if (aprod) {
                uint32_t aP = aBuf[cur ^ 1];
#pragma unroll
                for (int sl = 0; sl < 4; sl++)
                    produce_A_slice(aP + aDsw[sl], nb, aco, xsN[sl]);
            }
        }
        if (c + 2 < NCH) {
            if (aprod) {
                float4 xn = *reinterpret_cast<const float4*>(xNext);
                xsN[0] = xn.x; xsN[1] = xn.y; xsN[2] = xn.z; xsN[3] = xn.w;
            }
            xNext += NG;
        }

        uint32_t aB = aBuf[cur], bB = bBuf[cur];

        // software-pipelined fragment loop: load ks+1 before MMAs of ks
        uint32_t a[2][4][4], b[2][4][2];
#pragma unroll
        for (int mi = 0; mi < 3; mi++)
            ldmx4(a[0][mi], aB + aOff[mi]);
        if (big) ldmx4(a[0][3], aB + aOff[3]);
#pragma unroll
        for (int p = 0; p < 2; p++) {
            uint32_t r[4];
            ldmx4(r, bB + bOff[p]);
            b[0][2 * p][0] = r[0]; b[0][2 * p][1] = r[1];
            b[0][2 * p + 1][0] = r[2]; b[0][2 * p + 1][1] = r[3];
        }

#pragma unroll
        for (int ks = 0; ks < 4; ks++) {
            int cb = ks & 1, nxt = cb ^ 1;
            if (ks < 3) {
#pragma unroll
                for (int mi = 0; mi < 3; mi++)
                    ldmx4(a[nxt][mi], aB + (aOff[mi] ^ ((ks + 1) * 32)));
                if (big) ldmx4(a[nxt][3], aB + (aOff[3] ^ ((ks + 1) * 32)));
#pragma unroll
                for (int p = 0; p < 2; p++) {
                    uint32_t r[4];
                    ldmx4(r, bB + (bOff[p] ^ ((ks + 1) * 32)));
                    b[nxt][2 * p][0] = r[0]; b[nxt][2 * p][1] = r[1];
                    b[nxt][2 * p + 1][0] = r[2]; b[nxt][2 * p + 1][1] = r[3];
                }
            }
#pragma unroll
            for (int ni = 0; ni < 4; ni++)
#pragma unroll
                for (int mi = 0; mi < 3; mi++)
                    mma16816(acc[mi][ni], a[cb][mi], b[cb][ni]);
            if (big) {
#pragma unroll
                for (int ni = 0; ni < 4; ni++)
                    mma16816(acc[3][ni], a[cb][3], b[cb][ni]);
            }
        }
    }

    // epilogue: direct f32 stores from accumulators (mi=3 only on big tiles)
    float* obase = out + (size_t)Mstart * OUTF + Ntile * NT + wn * 32;
    int mcnt = big ? 4 : 3;
#pragma unroll
    for (int mi = 0; mi < 4; mi++) {
        if (mi >= mcnt) break;
        int r0 = mi * 16 + (lane >> 2);
#pragma unroll
        for (int ni = 0; ni < 4; ni++) {
            int cl = ni * 8 + (lane & 3) * 2;
            float2 v0 = make_float2(acc[mi][ni][0], acc[mi][ni][1]);
            float2 v1 = make_float2(acc[mi][ni][2], acc[mi][ni][3]);
            *reinterpret_cast<float2*>(obase + (size_t)r0 * OUTF + cl) = v0;
            *reinterpret_cast<float2*>(obase + (size_t)(r0 + 8) * OUTF + cl) = v1;
        }
    }
}

// ---------------- launch ----------------
extern "C" void kernel_launch(void* const* d_in, const int* in_sizes, int n_in,
                              void* d_out, int out_size) {
    const float* x    = (const float*)d_in[0];
    const float* grid = (const float*)d_in[1];
    const float* W    = (const float*)d_in[2];
    float* out = (float*)d_out;

    cudaFuncSetAttribute(gk_kernel, cudaFuncAttributeMaxDynamicSharedMemorySize, SMEM_DYN);

    dim3 tb(32, 8);
    wt_kernel<<<dim3(KTOT / 32, OUTF / 32), tb>>>(W);
    gk_kernel<<<GRID, THREADS, SMEM_DYN>>>(x, grid, out);
}

// round 15
// speedup vs baseline: 1.0498x; 1.0498x over previous
#include <cuda_runtime.h>
#include <cuda_fp16.h>
#include <cstdint>

#define DI __device__ __forceinline__

// ---------------- problem constants ----------------
constexpr int BATCH   = 16384;
constexpr int INF     = 512;
constexpr int OUTF    = 512;
constexpr int NG      = 8;
constexpr int KTOT    = INF * NG;    // 4096
constexpr int KC      = 64;          // K per chunk (128B fp16 row)
constexpr int NCH     = KTOT / KC;   // 64 chunks
constexpr int MT      = 64;          // M tile per CTA
constexpr int NT      = 128;         // N tile per CTA
constexpr int THREADS = 128;         // 4 warps
constexpr int STAGES  = 2;

// scheduling: 592 full-K tiles (one exact wave at 4 CTAs/SM x 148 SMs),
// remaining 432 tiles split-K into 4 quarter CTAs (16 chunks each)
constexpr int NTILES    = 1024;      // (16384/64) * (512/128)
constexpr int FULL_CTAS = 592;
constexpr int GRID      = FULL_CTAS + (NTILES - FULL_CTAS) * 4;   // 2320

constexpr int A_BYTES     = 64 * 128;             // 8 KB
constexpr int B_BYTES     = 128 * 128;            // 16 KB
constexpr int STAGE_BYTES = A_BYTES + B_BYTES;    // 24 KB
constexpr int SMEM_DYN    = STAGES * STAGE_BYTES + 1024;   // ~49 KB -> 4 CTAs/SM

// fp16 W transposed to [OUTF, KTOT], K contiguous
__device__ __half g_Wt[(size_t)OUTF * KTOT];

// ---------------- PTX helpers ----------------
DI uint32_t smem_u32(const void* p) {
    uint32_t a;
    asm("{ .reg .u64 t; cvta.to.shared.u64 t, %1; cvt.u32.u64 %0, t; }" : "=r"(a) : "l"(p));
    return a;
}

// pack (lo,hi) fp32 -> f16x2 and take 2^x on both halves in one MUFU op
DI uint32_t ex2_f16x2(float lo, float hi) {
    uint32_t d;
    asm("{ .reg .b32 t; cvt.rn.f16x2.f32 t, %1, %2; ex2.approx.f16x2 %0, t; }"
        : "=r"(d) : "f"(hi), "f"(lo));
    return d;
}

DI uint32_t swz(uint32_t off) { return off ^ ((off >> 3) & 0x70u); }

DI void ldmx4(uint32_t* r, uint32_t addr) {
    asm volatile("ldmatrix.sync.aligned.m8n8.x4.shared.b16 {%0,%1,%2,%3}, [%4];"
                 : "=r"(r[0]), "=r"(r[1]), "=r"(r[2]), "=r"(r[3]) : "r"(addr));
}

DI void mma16816(float* c, const uint32_t* a, const uint32_t* b) {
    asm volatile(
        "mma.sync.aligned.m16n8k16.row.col.f32.f16.f16.f32 "
        "{%0,%1,%2,%3}, {%4,%5,%6,%7}, {%8,%9}, {%0,%1,%2,%3};"
        : "+f"(c[0]), "+f"(c[1]), "+f"(c[2]), "+f"(c[3])
        : "r"(a[0]), "r"(a[1]), "r"(a[2]), "r"(a[3]), "r"(b[0]), "r"(b[1]));
}

DI void cp_async16(uint32_t dst, const void* src) {
    asm volatile("cp.async.cg.shared.global [%0], [%1], 16;" :: "r"(dst), "l"(src) : "memory");
}
#define CP_COMMIT() asm volatile("cp.async.commit_group;" ::: "memory")
#define CP_WAIT0()  asm volatile("cp.async.wait_group 0;" ::: "memory")

// ---------------- kernel 0: zero the output ----------------
__global__ void zero_kernel(float4* __restrict__ out) {
    int i = blockIdx.x * blockDim.x + threadIdx.x;
    float4 z = make_float4(0.f, 0.f, 0.f, 0.f);
#pragma unroll
    for (int r = 0; r < 4; r++)
        out[i + r * (int)(gridDim.x * blockDim.x)] = z;
}

// ---------------- kernel 1: W[K,N] f32 -> Wt[N,K] fp16 ----------------
__global__ void wt_kernel(const float* __restrict__ W) {
    __shared__ float tile[32][33];
    int k0 = blockIdx.x * 32, n0 = blockIdx.y * 32;
    int tx = threadIdx.x, ty = threadIdx.y;
#pragma unroll
    for (int i = 0; i < 32; i += 8)
        tile[ty + i][tx] = W[(size_t)(k0 + ty + i) * OUTF + n0 + tx];
    __syncthreads();
#pragma unroll
    for (int i = 0; i < 32; i += 8)
        g_Wt[(size_t)(n0 + ty + i) * KTOT + k0 + tx] = __float2half_rn(tile[tx][ty + i]);
}

// ---------------- kernel 2: fused basis + mma.sync GEMM ----------------

// B tile: 8 cp.async per thread; dst/src affine in slice index i
DI void produce_B(uint32_t bDst, const __half* bSrc) {
#pragma unroll
    for (int i = 0; i < 8; i++)
        cp_async16(bDst + i * 2048, (const void*)(bSrc + (size_t)i * 16 * KTOT));
}

// A slice: one feature -> 8 gaussian values -> one 16B store
DI void produce_A_slice(uint32_t aDst, const float* nb, float aco, float xf) {
    uint32_t pk[4];
#pragma unroll
    for (int q = 0; q < 4; q++) {
        float v0 = fmaf(xf, aco, nb[2 * q]);
        float v1 = fmaf(xf, aco, nb[2 * q + 1]);
        // exp(-u^2) = 2^(-(u*sqrt(log2 e))^2); both halves in one MUFU
        pk[q] = ex2_f16x2(-(v0 * v0), -(v1 * v1));
    }
    asm volatile("st.shared.v4.b32 [%0], {%1, %2, %3, %4};"
                 :: "r"(aDst), "r"(pk[0]), "r"(pk[1]), "r"(pk[2]), "r"(pk[3])
                 : "memory");
}

__global__ void __launch_bounds__(THREADS, 4)
gk_kernel(const float* __restrict__ x, const float* __restrict__ grid,
          float* __restrict__ out)
{
    extern __shared__ char smem[];
    uint32_t sb = (smem_u32(smem) + 1023u) & ~1023u;

    int tid  = threadIdx.x;
    int lane = tid & 31;
    int wid  = tid >> 5;
    int bid  = blockIdx.x;

    // decode: full tile (all 64 chunks, STG) or quarter tile (16 chunks, RED)
    bool full;
    int tileId, c0, c1;
    if (bid < FULL_CTAS) {
        full = true;  tileId = bid;  c0 = 0;  c1 = NCH;
    } else {
        full = false;
        int q  = bid - FULL_CTAS;
        tileId = FULL_CTAS + (q >> 2);
        int kq = q & 3;
        c0 = kq * (NCH / 4);  c1 = c0 + (NCH / 4);
    }
    int Mtile = tileId & 255;        // m-major: consecutive tiles share B slab
    int Ntile = tileId >> 8;

    float aco = 1.75f * 1.2011224087864498f;   // (1/h)*sqrt(log2 e), h = 4/7
    float nb[8];
#pragma unroll
    for (int g = 0; g < 8; g++) nb[g] = -grid[g] * aco;

    uint32_t aBuf[STAGES], bBuf[STAGES];
#pragma unroll
    for (int s = 0; s < STAGES; s++) {
        aBuf[s] = sb + s * STAGE_BYTES;
        bBuf[s] = aBuf[s] + A_BYTES;
    }

    // ---- hoisted producer state ----
    int n0  = tid >> 3, seg = tid & 7;
    uint32_t bD0 = swz((uint32_t)(n0 * 128 + seg * 16));   // slice-invariant swizzle
    const __half* bSrcNext = g_Wt + (size_t)(Ntile * NT + n0) * KTOT + seg * 8 + c0 * KC;
    int m = tid >> 1, half = tid & 1;
    uint32_t aDsw[4];
#pragma unroll
    for (int sl = 0; sl < 4; sl++)
        aDsw[sl] = swz((uint32_t)(m * 128 + (half * 4 + sl) * 16));
    const float* xNext = x + (size_t)(Mtile * MT + m) * INF + half * 4 + c0 * NG;

    // warp tiling: 4 warps = 1(M) x 4(N); warp tile 64x32
    int wn = wid;

    uint32_t aOff[4], bOff[2];
#pragma unroll
    for (int mi = 0; mi < 4; mi++) {
        int row = mi * 16 + (lane & 15);
        int u   = lane >> 4;
        aOff[mi] = swz((uint32_t)(row * 128 + u * 16));
    }
#pragma unroll
    for (int p = 0; p < 2; p++) {
        int row = wn * 32 + p * 16 + ((lane >> 4) & 1) * 8 + (lane & 7);
        int u   = (lane >> 3) & 1;
        bOff[p] = swz((uint32_t)(row * 128 + u * 16));
    }

    float acc[4][4][4];
#pragma unroll
    for (int mi = 0; mi < 4; mi++)
#pragma unroll
        for (int ni = 0; ni < 4; ni++)
#pragma unroll
            for (int q = 0; q < 4; q++) acc[mi][ni][q] = 0.0f;

    // prologue: stage chunk c0; prefetch x for c0+1
    float xsN[4];
    {
        produce_B(bBuf[0] + bD0, bSrcNext);
        bSrcNext += KC;
        float4 x0 = *reinterpret_cast<const float4*>(xNext);
        xNext += NG;
        float xs0[4] = {x0.x, x0.y, x0.z, x0.w};
#pragma unroll
        for (int sl = 0; sl < 4; sl++)
            produce_A_slice(aBuf[0] + aDsw[sl], nb, aco, xs0[sl]);
        CP_COMMIT();
        float4 x1 = *reinterpret_cast<const float4*>(xNext);
        xNext += NG;
        xsN[0] = x1.x; xsN[1] = x1.y; xsN[2] = x1.z; xsN[3] = x1.w;
    }

    for (int c = c0; c < c1; c++) {
        CP_WAIT0();
        __syncthreads();

        int cur = (c - c0) & 1;
        bool doprod = (c + 1 < c1);
        if (doprod) {
            produce_B(bBuf[cur ^ 1] + bD0, bSrcNext);
            bSrcNext += KC;
            CP_COMMIT();
            uint32_t aP = aBuf[cur ^ 1];
#pragma unroll
            for (int sl = 0; sl < 4; sl++)
                produce_A_slice(aP + aDsw[sl], nb, aco, xsN[sl]);
        }
        if (c + 2 < c1) {
            float4 xn = *reinterpret_cast<const float4*>(xNext);
            xNext += NG;
            xsN[0] = xn.x; xsN[1] = xn.y; xsN[2] = xn.z; xsN[3] = xn.w;
        }

        uint32_t aB = aBuf[cur], bB = bBuf[cur];

        // software-pipelined fragment loop: load ks+1 before MMAs of ks
        uint32_t a[2][4][4], b[2][4][2];
#pragma unroll
        for (int mi = 0; mi < 4; mi++)
            ldmx4(a[0][mi], aB + aOff[mi]);
#pragma unroll
        for (int p = 0; p < 2; p++) {
            uint32_t r[4];
            ldmx4(r, bB + bOff[p]);
            b[0][2 * p][0] = r[0]; b[0][2 * p][1] = r[1];
            b[0][2 * p + 1][0] = r[2]; b[0][2 * p + 1][1] = r[3];
        }

#pragma unroll
        for (int ks = 0; ks < 4; ks++) {
            int cb = ks & 1, nxt = cb ^ 1;
            if (ks < 3) {
#pragma unroll
                for (int mi = 0; mi < 4; mi++)
                    ldmx4(a[nxt][mi], aB + (aOff[mi] ^ ((ks + 1) * 32)));
#pragma unroll
                for (int p = 0; p < 2; p++) {
                    uint32_t r[4];
                    ldmx4(r, bB + (bOff[p] ^ ((ks + 1) * 32)));
                    b[nxt][2 * p][0] = r[0]; b[nxt][2 * p][1] = r[1];
                    b[nxt][2 * p + 1][0] = r[2]; b[nxt][2 * p + 1][1] = r[3];
                }
            }
#pragma unroll
            for (int ni = 0; ni < 4; ni++)
#pragma unroll
                for (int mi = 0; mi < 4; mi++)
                    mma16816(acc[mi][ni], a[cb][mi], b[cb][ni]);
        }
    }

    // epilogue: full tiles store directly; quarter tiles accumulate via RED
    float* obase = out + (size_t)(Mtile * MT) * OUTF + Ntile * NT + wn * 32;
    if (full) {
#pragma unroll
        for (int mi = 0; mi < 4; mi++) {
            int r0 = mi * 16 + (lane >> 2);
#pragma unroll
            for (int ni = 0; ni < 4; ni++) {
                int cl = ni * 8 + (lane & 3) * 2;
                float2 v0 = make_float2(acc[mi][ni][0], acc[mi][ni][1]);
                float2 v1 = make_float2(acc[mi][ni][2], acc[mi][ni][3]);
                *reinterpret_cast<float2*>(obase + (size_t)r0 * OUTF + cl) = v0;
                *reinterpret_cast<float2*>(obase + (size_t)(r0 + 8) * OUTF + cl) = v1;
            }
        }
    } else {
#pragma unroll
        for (int mi = 0; mi < 4; mi++) {
            int r0 = mi * 16 + (lane >> 2);
#pragma unroll
            for (int ni = 0; ni < 4; ni++) {
                int cl = ni * 8 + (lane & 3) * 2;
                float* p0 = obase + (size_t)r0 * OUTF + cl;
                float* p1 = obase + (size_t)(r0 + 8) * OUTF + cl;
                atomicAdd(p0,     acc[mi][ni][0]);
                atomicAdd(p0 + 1, acc[mi][ni][1]);
                atomicAdd(p1,     acc[mi][ni][2]);
                atomicAdd(p1 + 1, acc[mi][ni][3]);
            }
        }
    }
}

// ---------------- launch ----------------
extern "C" void kernel_launch(void* const* d_in, const int* in_sizes, int n_in,
                              void* d_out, int out_size) {
    const float* x    = (const float*)d_in[0];
    const float* grid = (const float*)d_in[1];
    const float* W    = (const float*)d_in[2];
    float* out = (float*)d_out;

    cudaFuncSetAttribute(gk_kernel, cudaFuncAttributeMaxDynamicSharedMemorySize, SMEM_DYN);

    // zero output (quarter tiles accumulate with RED): 8.4M floats = 2.1M float4
    zero_kernel<<<2048, 256>>>((float4*)out);
    dim3 tb(32, 8);
    wt_kernel<<<dim3(KTOT / 32, OUTF / 32), tb>>>(W);
    gk_kernel<<<GRID, THREADS, SMEM_DYN>>>(x, grid, out);
}